// round 16
// baseline (speedup 1.0000x reference)
#include <cuda_runtime.h>
#include <cuda_bf16.h>

// Shapes (fixed problem): B=4, S=256, D=16 (DD=256), H=128, K=16.
// B,S,K,H derived at runtime; D=16 / DD=256 assumed by the process kernel.

#define MAXH   128
#define MAXINT 129          // at most H thresholds -> H+1 intervals
#define MAXP   (4*256*256)  // 262144 pairs
#define MAXBS  (4*256)
#define DVAL   16
#define DDVAL  256

// -------- device scratch (no allocations allowed) --------
__device__ __align__(16) float g_A[MAXINT][DDVAL];   // per-interval slope  (incl. w1*w2 sums)
__device__ __align__(16) float g_C[MAXINT][DDVAL];   // per-interval offset (incl. b1*w2 sums + b2)
__device__ __align__(16) float g_ee1[MAXBS * DVAL];  // relu(emb1[indicator])
__device__ __align__(16) float g_ee2[MAXBS * DVAL];  // relu(emb2[indicator])
__device__ float g_valid[MAXBS];
__device__ float g_thresh[MAXH];
__device__ int   g_nth;
__device__ float g_t[MAXP];
__device__ int   g_int[MAXP];
__device__ int   g_order[MAXP];
__device__ int   g_hist[MAXINT];
__device__ int   g_cursor[MAXINT];
__device__ int   g_off[MAXINT + 1];
__device__ int   g_nact;

// ---------------------------------------------------------------------------
// Kernel 1: per-row prep (valid mask, relu'd embeddings, sorted thresholds,
// zero histograms/cursors). One block, 256 threads.
// ---------------------------------------------------------------------------
__global__ void __launch_bounds__(256) prep_kernel(
    const float* __restrict__ ets,      // [BS, K]
    const int*   __restrict__ ind,      // [BS]
    const float* __restrict__ w1,       // [H]
    const float* __restrict__ b1,       // [H]
    const float* __restrict__ emb1,     // [K+1, D]
    const float* __restrict__ emb2,     // [K+1, D]
    int BS, int K, int H)
{
    int tid = threadIdx.x;

    // valid[b,s] = !all(event_type_seq == 0)
    for (int s = tid; s < BS; s += 256) {
        bool nz = false;
        const float* row = ets + (long)s * K;
        for (int k = 0; k < K; k++) nz |= (row[k] != 0.0f);
        g_valid[s] = nz ? 1.0f : 0.0f;
    }

    // relu'd embedding gathers
    for (int idx = tid; idx < BS * DVAL; idx += 256) {
        int s = idx >> 4, d = idx & 15;
        int id = ind[s];
        g_ee1[idx] = fmaxf(emb1[id * DVAL + d], 0.0f);
        g_ee2[idx] = fmaxf(emb2[id * DVAL + d], 0.0f);
    }

    // zero hist/cursor (must be re-done every replay)
    for (int x = tid; x < MAXINT; x += 256) { g_hist[x] = 0; g_cursor[x] = 0; }

    // thresholds theta = -b1/w1 where the relu flips sign within t >= 0
    __shared__ float th[MAXH];
    __shared__ int   has[MAXH];
    __shared__ int   cnt;
    if (tid == 0) cnt = 0;
    if (tid < H) {
        float w = w1[tid], b = b1[tid];
        bool h = (w > 0.0f && b < 0.0f) || (w < 0.0f && b > 0.0f);
        th[tid]  = h ? (-b / w) : 3.0e38f;
        has[tid] = h ? 1 : 0;
    }
    __syncthreads();
    if (tid < H && has[tid]) {
        float v = th[tid];
        int rank = 0;
        for (int n = 0; n < H; n++)
            if (has[n] && (th[n] < v || (th[n] == v && n < tid))) rank++;
        g_thresh[rank] = v;
        atomicAdd(&cnt, 1);
    }
    __syncthreads();
    if (tid == 0) g_nth = cnt;
}

// ---------------------------------------------------------------------------
// Kernel 2: per-interval affine tables. Block I handles interval I:
//   A_I[m] = sum_{n active in I} w1[n]*w2[n,m]
//   C_I[m] = sum_{n active in I} b1[n]*w2[n,m] + b2[m]
// Activity decided at the interval midpoint (boundary units contribute ~0).
// ---------------------------------------------------------------------------
__global__ void __launch_bounds__(256) tables_kernel(
    const float* __restrict__ w1, const float* __restrict__ b1,
    const float* __restrict__ w2, const float* __restrict__ b2, int H)
{
    int I = blockIdx.x;
    int nth = g_nth;
    if (I > nth) return;

    float tmid;
    if (nth == 0)       tmid = 1.0f;
    else if (I == 0)    tmid = 0.5f * g_thresh[0];
    else if (I == nth)  tmid = g_thresh[nth - 1] + 1.0f;
    else                tmid = 0.5f * (g_thresh[I - 1] + g_thresh[I]);

    __shared__ float sw[MAXH], sb[MAXH];
    for (int n = threadIdx.x; n < H; n += 256) { sw[n] = w1[n]; sb[n] = b1[n]; }
    __syncthreads();

    int m = threadIdx.x;  // DD == 256 == blockDim
    float a = 0.0f, c = b2[m];
    for (int n = 0; n < H; n++) {
        float w = sw[n], b = sb[n];
        if (fmaf(tmid, w, b) > 0.0f) {
            float wv = w2[n * DDVAL + m];
            a = fmaf(w, wv, a);
            c = fmaf(b, wv, c);
        }
    }
    g_A[I][m] = a;
    g_C[I][m] = c;
}

// ---------------------------------------------------------------------------
// Kernel 3: per-pair t, interval id, zero output, block-local histogram.
// ---------------------------------------------------------------------------
__global__ void __launch_bounds__(256) bin_kernel(
    const float* __restrict__ dt, float* __restrict__ out, int S, int P)
{
    __shared__ int sh[MAXINT];
    for (int x = threadIdx.x; x < MAXINT; x += 256) sh[x] = 0;
    __syncthreads();

    int SS = S * S;
    int nth = g_nth;
    for (int p = blockIdx.x * 256 + threadIdx.x; p < P; p += gridDim.x * 256) {
        out[p] = 0.0f;
        int b   = p / SS;
        int rem = p - b * SS;
        int i   = rem / S;
        int j   = rem - i * S;
        float traw = dt[p];
        float mk = g_valid[b * S + i] * g_valid[b * S + j];
        if (traw > 0.0f && mk > 0.0f) {
            float t = __logf(traw + 1.0f);
            int lo = 0, hi = nth;                 // count of thresholds <= t
            while (lo < hi) {
                int mid = (lo + hi) >> 1;
                if (g_thresh[mid] <= t) lo = mid + 1; else hi = mid;
            }
            g_t[p]   = t;
            g_int[p] = lo;
            atomicAdd(&sh[lo], 1);
        } else {
            g_int[p] = -1;
        }
    }
    __syncthreads();
    for (int x = threadIdx.x; x < MAXINT; x += 256) {
        int v = sh[x];
        if (v) atomicAdd(&g_hist[x], v);
    }
}

// ---------------------------------------------------------------------------
// Kernel 4: exclusive scan over <=129 bins (serial, trivial size).
// ---------------------------------------------------------------------------
__global__ void scan_kernel()
{
    if (threadIdx.x == 0) {
        int acc = 0, nint = g_nth + 1;
        for (int q = 0; q < nint; q++) { g_off[q] = acc; acc += g_hist[q]; }
        g_off[nint] = acc;
        g_nact = acc;
    }
}

// ---------------------------------------------------------------------------
// Kernel 5: scatter pair ids into interval-sorted order (warp-aggregated atomics).
// ---------------------------------------------------------------------------
__global__ void __launch_bounds__(256) scatter_kernel(int P)
{
    for (int p = blockIdx.x * 256 + threadIdx.x; p < P; p += gridDim.x * 256) {
        int I = g_int[p];
        if (I >= 0) {
            int lane = threadIdx.x & 31;
            unsigned peers = __match_any_sync(__activemask(), I);
            int leader = __ffs(peers) - 1;
            int rank = __popc(peers & ((1u << lane) - 1));
            int base = 0;
            if (lane == leader) base = atomicAdd(&g_cursor[I], __popc(peers));
            base = __shfl_sync(peers, base, leader);
            g_order[g_off[I] + base + rank] = p;
        }
    }
}

// ---------------------------------------------------------------------------
// Kernel 6: main compute. One warp per (interval-sorted) pair:
//   z_m = fma(t, A_I[m], C_I[m]);  out = sum_m softplus(z_m)*ee1[d]*ee2[e]
// lane handles m = lane*8..lane*8+7 -> d = lane>>1 (constant per lane),
// e = 0..7 (even lane) / 8..15 (odd lane). Sorted order => A/C rows L1-hit.
// ---------------------------------------------------------------------------
__device__ __forceinline__ float softplus_f(float z)
{
    float e = __expf(-fabsf(z));
    return fmaxf(z, 0.0f) + __logf(1.0f + e);
}

__global__ void __launch_bounds__(256) proc_kernel(float* __restrict__ out, int S, int SS)
{
    int wid  = threadIdx.x >> 5;
    int lane = threadIdx.x & 31;
    int sidx = blockIdx.x * 8 + wid;
    if (sidx >= g_nact) return;

    int   p = g_order[sidx];
    float t = g_t[p];
    int   I = g_int[p];

    int b   = p / SS;
    int rem = p - b * SS;
    int i   = rem / S;
    int j   = rem - i * S;

    const float4* A4 = reinterpret_cast<const float4*>(g_A[I]);
    const float4* C4 = reinterpret_cast<const float4*>(g_C[I]);
    float4 a0 = A4[lane * 2 + 0], a1 = A4[lane * 2 + 1];
    float4 c0 = C4[lane * 2 + 0], c1 = C4[lane * 2 + 1];

    float e1 = g_ee1[(b * S + i) * DVAL + (lane >> 1)];
    const float4* E2 = reinterpret_cast<const float4*>(&g_ee2[(b * S + j) * DVAL]);
    int eb = (lane & 1) * 2;
    float4 w0 = E2[eb], w1v = E2[eb + 1];

    float acc =
          softplus_f(fmaf(t, a0.x, c0.x)) * w0.x
        + softplus_f(fmaf(t, a0.y, c0.y)) * w0.y
        + softplus_f(fmaf(t, a0.z, c0.z)) * w0.z
        + softplus_f(fmaf(t, a0.w, c0.w)) * w0.w
        + softplus_f(fmaf(t, a1.x, c1.x)) * w1v.x
        + softplus_f(fmaf(t, a1.y, c1.y)) * w1v.y
        + softplus_f(fmaf(t, a1.z, c1.z)) * w1v.z
        + softplus_f(fmaf(t, a1.w, c1.w)) * w1v.w;
    acc *= e1;

    #pragma unroll
    for (int off = 16; off; off >>= 1)
        acc += __shfl_down_sync(0xffffffffu, acc, off);

    if (lane == 0) out[p] = acc;  // pos and pad_mask are exactly 1 for active pairs
}

// ---------------------------------------------------------------------------
extern "C" void kernel_launch(void* const* d_in, const int* in_sizes, int n_in,
                              void* d_out, int out_size)
{
    const int P  = in_sizes[0];        // B*S*S
    const int BS = in_sizes[2];        // B*S
    const int S  = P / BS;
    const int K  = in_sizes[1] / BS;

    // num_types may be passed as a 1-element scalar input at index 3
    const int base = (in_sizes[3] == 1) ? 4 : 3;

    const float* dt   = (const float*)d_in[0];
    const float* ets  = (const float*)d_in[1];
    const int*   ind  = (const int*)  d_in[2];
    const float* w1   = (const float*)d_in[base + 0];
    const float* b1   = (const float*)d_in[base + 1];
    const float* w2   = (const float*)d_in[base + 2];
    const float* b2   = (const float*)d_in[base + 3];
    const float* emb1 = (const float*)d_in[base + 4];
    const float* emb2 = (const float*)d_in[base + 5];
    const int H = in_sizes[base + 0];

    float* out = (float*)d_out;

    prep_kernel<<<1, 256>>>(ets, ind, w1, b1, emb1, emb2, BS, K, H);
    tables_kernel<<<MAXINT, 256>>>(w1, b1, w2, b2, H);
    bin_kernel<<<592, 256>>>(dt, out, S, P);
    scan_kernel<<<1, 32>>>();
    scatter_kernel<<<592, 256>>>(P);
    int pb = (P + 7) / 8;                 // one warp per pair, 8 warps/block
    proc_kernel<<<pb, 256>>>(out, S, S * S);
}